// round 2
// baseline (speedup 1.0000x reference)
#include <cuda_runtime.h>
#include <cuda_bf16.h>
#include <cstdint>

// Problem constants
#define BB   8
#define SS   1024
#define DD   512
#define HH   8
#define HDQ  64
#define DFF  2048
#define ROWS (BB*SS)          // 8192
#define BH   (BB*HH)          // 64

// ---------------- scratch (static __device__ arrays; no allocation APIs) ----
__device__ float g_h  [ROWS*DD];
__device__ float g_q  [ROWS*DD];
__device__ float g_k  [ROWS*DD];
__device__ float g_v  [ROWS*DD];
__device__ float g_ctx[ROWS*DD];
__device__ float g_y  [ROWS*DD];
__device__ float g_h2 [ROWS*DD];
__device__ float g_ff [ROWS*DFF];

// ---------------------------------------------------------------- rmsnorm ---
// one block per row of 512; 128 threads x float4
__global__ void __launch_bounds__(128) rmsnorm_kernel(
    const float* __restrict__ x, const float* __restrict__ w,
    float* __restrict__ out)
{
    const int row = blockIdx.x;
    const int tid = threadIdx.x;
    const float4 v = reinterpret_cast<const float4*>(x + (size_t)row * DD)[tid];
    float ss = v.x*v.x + v.y*v.y + v.z*v.z + v.w*v.w;

    __shared__ float red[4];
    #pragma unroll
    for (int o = 16; o; o >>= 1) ss += __shfl_xor_sync(0xffffffffu, ss, o);
    if ((tid & 31) == 0) red[tid >> 5] = ss;
    __syncthreads();
    if (tid < 32) {
        float t = 0.f;
        if (tid < 4) t = red[tid];
        t += __shfl_xor_sync(0xffffffffu, t, 1);
        t += __shfl_xor_sync(0xffffffffu, t, 2);
        if (tid == 0) red[0] = t;
    }
    __syncthreads();
    const float tot = red[0];

    const float r = rsqrtf(tot * (1.0f / DD) + 1e-6f);
    const float4 g = reinterpret_cast<const float4*>(w)[tid];
    float4 o;
    o.x = v.x * g.x * r; o.y = v.y * g.y * r;
    o.z = v.z * g.z * r; o.w = v.w * g.w * r;
    reinterpret_cast<float4*>(out + (size_t)row * DD)[tid] = o;
}

// --------------------------------------------------------------- SGEMM NT ---
// C[M,N] = A[M,K] * B[N,K]^T  (+epilogue). 128x128 tile, K-step 8, 256 thr,
// 8x8 microtile per thread. M,N mult of 128; K mult of 8 (all true here).
// epi: 0 = plain, 1 = relu, 2 = residual add (C = R + A*B^T)
__global__ void __launch_bounds__(256, 2) sgemm_nt(
    const float* __restrict__ A, const float* __restrict__ B,
    float* __restrict__ C, const float* __restrict__ R,
    int K, int lda, int ldb, int ldc, int epi)
{
    __shared__ float As[8][128];
    __shared__ float Bs[8][128];
    const int tid = threadIdx.x;
    const int tx = tid & 15, ty = tid >> 4;
    const int m0 = blockIdx.y * 128, n0 = blockIdx.x * 128;
    const int lr = tid >> 1, lk = (tid & 1) * 4;
    const float* Ag = A + (size_t)(m0 + lr) * lda + lk;
    const float* Bg = B + (size_t)(n0 + lr) * ldb + lk;

    float acc[8][8];
    #pragma unroll
    for (int i = 0; i < 8; ++i)
        #pragma unroll
        for (int j = 0; j < 8; ++j) acc[i][j] = 0.f;

    for (int k0 = 0; k0 < K; k0 += 8) {
        const float4 a4 = *reinterpret_cast<const float4*>(Ag + k0);
        const float4 b4 = *reinterpret_cast<const float4*>(Bg + k0);
        __syncthreads();
        As[lk+0][lr] = a4.x; As[lk+1][lr] = a4.y;
        As[lk+2][lr] = a4.z; As[lk+3][lr] = a4.w;
        Bs[lk+0][lr] = b4.x; Bs[lk+1][lr] = b4.y;
        Bs[lk+2][lr] = b4.z; Bs[lk+3][lr] = b4.w;
        __syncthreads();
        #pragma unroll
        for (int kk = 0; kk < 8; ++kk) {
            float a[8], b[8];
            *reinterpret_cast<float4*>(a)     = *reinterpret_cast<const float4*>(&As[kk][ty*4]);
            *reinterpret_cast<float4*>(a + 4) = *reinterpret_cast<const float4*>(&As[kk][64 + ty*4]);
            *reinterpret_cast<float4*>(b)     = *reinterpret_cast<const float4*>(&Bs[kk][tx*4]);
            *reinterpret_cast<float4*>(b + 4) = *reinterpret_cast<const float4*>(&Bs[kk][64 + tx*4]);
            #pragma unroll
            for (int i = 0; i < 8; ++i)
                #pragma unroll
                for (int j = 0; j < 8; ++j)
                    acc[i][j] += a[i] * b[j];
        }
    }

    #pragma unroll
    for (int i = 0; i < 8; ++i) {
        const int r = m0 + ((i < 4) ? (ty*4 + i) : (64 + ty*4 + i - 4));
        #pragma unroll
        for (int j = 0; j < 8; ++j) {
            const int c = n0 + ((j < 4) ? (tx*4 + j) : (64 + tx*4 + j - 4));
            const size_t idx = (size_t)r * ldc + c;
            float val = acc[i][j];
            if (epi == 1)      val = fmaxf(val, 0.f);
            else if (epi == 2) val += R[idx];
            C[idx] = val;
        }
    }
}

// ------------------------------------------------------- fused attention ----
// Flash-style: per CTA one (bh, 64-row q-tile). Online softmax over K-tiles
// of 64. Bias added to raw scores (T5: no 1/sqrt(d)).
// Thread map: 256 threads = 16x16 (tx, ty). Each thread owns score/prob block
// rows ty*4+i, cols tx*4+j, and output block rows ty*4+i, dims tx*4+j.
// smem (dynamic, 67584 B):
//   Qst[64][68]  Q tile transposed (d-major)  @ 0
//   Kst[64][68]  K tile transposed (d-major)  @ 17408
//   Vs [64][64]  V tile natural               @ 34816
//   Ps [64][64]  prob tile                    @ 51200
#define FA_SMEM_BYTES 67584

__global__ void __launch_bounds__(256, 2) flash_attn_kernel(
    const float* __restrict__ Q, const float* __restrict__ Kg,
    const float* __restrict__ V, const float* __restrict__ bias,
    float* __restrict__ O)
{
    extern __shared__ float smem[];
    float (*Qst)[68] = reinterpret_cast<float(*)[68]>(smem);
    float (*Kst)[68] = reinterpret_cast<float(*)[68]>(smem + 17408/4);
    float (*Vs )[64] = reinterpret_cast<float(*)[64]>(smem + 34816/4);
    float (*Ps )[64] = reinterpret_cast<float(*)[64]>(smem + 51200/4);

    const int tid = threadIdx.x;
    const int tx = tid & 15, ty = tid >> 4;
    const int q0 = blockIdx.x * 64;
    const int bh = blockIdx.y;
    const int b = bh >> 3, h = bh & 7;

    const float* Qb = Q  + (size_t)b * SS * DD + h * HDQ;   // [S][D] rows, head slice
    const float* Kb = Kg + (size_t)b * SS * DD + h * HDQ;
    const float* Vb = V  + (size_t)b * SS * DD + h * HDQ;
    const float* Bb = bias + (size_t)bh * SS * SS;

    // ---- load Q tile (64 rows x 64 dims), store transposed ----
    #pragma unroll
    for (int t = 0; t < 4; ++t) {
        const int idx = tid + t * 256;          // 0..1023 float4 slots
        const int row = idx >> 4;               // 0..63
        const int dv  = idx & 15;               // float4 index within row
        const float4 qv = *reinterpret_cast<const float4*>(
            Qb + (size_t)(q0 + row) * DD + dv * 4);
        Qst[dv*4+0][row] = qv.x; Qst[dv*4+1][row] = qv.y;
        Qst[dv*4+2][row] = qv.z; Qst[dv*4+3][row] = qv.w;
    }

    float o[4][4];
    float m[4], l[4];
    #pragma unroll
    for (int i = 0; i < 4; ++i) {
        m[i] = -3.4e38f; l[i] = 0.f;
        #pragma unroll
        for (int j = 0; j < 4; ++j) o[i][j] = 0.f;
    }
    __syncthreads();

    for (int k0 = 0; k0 < SS; k0 += 64) {
        // ---- stage K,V tile loads into registers ----
        float4 kreg[4], vreg[4];
        #pragma unroll
        for (int t = 0; t < 4; ++t) {
            const int idx = tid + t * 256;
            const int row = idx >> 4, dv = idx & 15;
            kreg[t] = *reinterpret_cast<const float4*>(
                Kb + (size_t)(k0 + row) * DD + dv * 4);
            vreg[t] = *reinterpret_cast<const float4*>(
                Vb + (size_t)(k0 + row) * DD + dv * 4);
        }
        __syncthreads();   // previous PV reads of Vs/Ps done
        #pragma unroll
        for (int t = 0; t < 4; ++t) {
            const int idx = tid + t * 256;
            const int row = idx >> 4, dv = idx & 15;
            Kst[dv*4+0][row] = kreg[t].x; Kst[dv*4+1][row] = kreg[t].y;
            Kst[dv*4+2][row] = kreg[t].z; Kst[dv*4+3][row] = kreg[t].w;
            *reinterpret_cast<float4*>(&Vs[row][dv*4]) = vreg[t];
        }
        __syncthreads();

        // ---- scores s = Q*K^T + bias (4x4 per thread) ----
        float s[4][4];
        #pragma unroll
        for (int i = 0; i < 4; ++i) {
            const float4 bv = *reinterpret_cast<const float4*>(
                Bb + (size_t)(q0 + ty*4 + i) * SS + k0 + tx*4);
            s[i][0] = bv.x; s[i][1] = bv.y; s[i][2] = bv.z; s[i][3] = bv.w;
        }
        #pragma unroll
        for (int kk = 0; kk < 64; ++kk) {
            const float4 qv = *reinterpret_cast<const float4*>(&Qst[kk][ty*4]);
            const float4 kv = *reinterpret_cast<const float4*>(&Kst[kk][tx*4]);
            const float qa[4] = {qv.x, qv.y, qv.z, qv.w};
            const float ka[4] = {kv.x, kv.y, kv.z, kv.w};
            #pragma unroll
            for (int i = 0; i < 4; ++i)
                #pragma unroll
                for (int j = 0; j < 4; ++j)
                    s[i][j] += qa[i] * ka[j];
        }

        // ---- online softmax update ----
        #pragma unroll
        for (int i = 0; i < 4; ++i) {
            float tm = fmaxf(fmaxf(s[i][0], s[i][1]), fmaxf(s[i][2], s[i][3]));
            #pragma unroll
            for (int off = 1; off < 16; off <<= 1)
                tm = fmaxf(tm, __shfl_xor_sync(0xffffffffu, tm, off, 16));
            const float mn = fmaxf(m[i], tm);
            const float scale = __expf(m[i] - mn);   // 0 on first tile (m=-inf)
            m[i] = mn;
            float rs = 0.f;
            #pragma unroll
            for (int j = 0; j < 4; ++j) {
                s[i][j] = __expf(s[i][j] - mn);
                rs += s[i][j];
            }
            #pragma unroll
            for (int off = 1; off < 16; off <<= 1)
                rs += __shfl_xor_sync(0xffffffffu, rs, off, 16);
            l[i] = l[i] * scale + rs;
            #pragma unroll
            for (int j = 0; j < 4; ++j) o[i][j] *= scale;
            // stash probs
            *reinterpret_cast<float4*>(&Ps[ty*4 + i][tx*4]) =
                make_float4(s[i][0], s[i][1], s[i][2], s[i][3]);
        }
        __syncthreads();

        // ---- O += P * V ----
        #pragma unroll
        for (int kk = 0; kk < 64; kk += 4) {
            float4 pr[4];
            #pragma unroll
            for (int i = 0; i < 4; ++i)
                pr[i] = *reinterpret_cast<const float4*>(&Ps[ty*4 + i][kk]);
            #pragma unroll
            for (int t = 0; t < 4; ++t) {
                const float4 vv = *reinterpret_cast<const float4*>(&Vs[kk + t][tx*4]);
                const float pw[4] = {
                    t == 0 ? pr[0].x : t == 1 ? pr[0].y : t == 2 ? pr[0].z : pr[0].w,
                    t == 0 ? pr[1].x : t == 1 ? pr[1].y : t == 2 ? pr[1].z : pr[1].w,
                    t == 0 ? pr[2].x : t == 1 ? pr[2].y : t == 2 ? pr[2].z : pr[2].w,
                    t == 0 ? pr[3].x : t == 1 ? pr[3].y : t == 2 ? pr[3].z : pr[3].w };
                #pragma unroll
                for (int i = 0; i < 4; ++i) {
                    o[i][0] += pw[i] * vv.x;
                    o[i][1] += pw[i] * vv.y;
                    o[i][2] += pw[i] * vv.z;
                    o[i][3] += pw[i] * vv.w;
                }
            }
        }
        __syncthreads();
    }

    // ---- normalize and write ctx in [B,S,D] layout ----
    #pragma unroll
    for (int i = 0; i < 4; ++i) {
        const float inv = 1.0f / l[i];
        float* op = O + (size_t)b * SS * DD + (size_t)(q0 + ty*4 + i) * DD
                      + h * HDQ + tx * 4;
        *reinterpret_cast<float4*>(op) =
            make_float4(o[i][0]*inv, o[i][1]*inv, o[i][2]*inv, o[i][3]*inv);
    }
}

// ------------------------------------------------------------------ host ----
extern "C" void kernel_launch(void* const* d_in, const int* in_sizes, int n_in,
                              void* d_out, int out_size)
{
    const float* Wk   = (const float*)d_in[0];
    const float* Wo   = (const float*)d_in[1];
    const float* Wq   = (const float*)d_in[2];
    const float* Wv   = (const float*)d_in[3];
    const float* gm1  = (const float*)d_in[4];
    const float* wi   = (const float*)d_in[5];
    const float* wo   = (const float*)d_in[6];
    const float* gm2  = (const float*)d_in[7];
    const float* x    = (const float*)d_in[8];
    const float* bias = (const float*)d_in[9];
    float* out = (float*)d_out;

    float *h, *q, *k, *v, *ctx, *y, *h2, *ff;
    cudaGetSymbolAddress((void**)&h,   g_h);
    cudaGetSymbolAddress((void**)&q,   g_q);
    cudaGetSymbolAddress((void**)&k,   g_k);
    cudaGetSymbolAddress((void**)&v,   g_v);
    cudaGetSymbolAddress((void**)&ctx, g_ctx);
    cudaGetSymbolAddress((void**)&y,   g_y);
    cudaGetSymbolAddress((void**)&h2,  g_h2);
    cudaGetSymbolAddress((void**)&ff,  g_ff);

    cudaFuncSetAttribute(flash_attn_kernel,
                         cudaFuncAttributeMaxDynamicSharedMemorySize,
                         FA_SMEM_BYTES);

    // 1. h = rmsnorm(x) * g1
    rmsnorm_kernel<<<ROWS, 128>>>(x, gm1, h);

    // 2-4. q/k/v = h @ W^T      (M=8192, N=512, K=512)
    const dim3 g512(DD / 128, ROWS / 128);
    sgemm_nt<<<g512, 256>>>(h, Wq, q, nullptr, DD, DD, DD, DD, 0);
    sgemm_nt<<<g512, 256>>>(h, Wk, k, nullptr, DD, DD, DD, DD, 0);
    sgemm_nt<<<g512, 256>>>(h, Wv, v, nullptr, DD, DD, DD, DD, 0);

    // 5. fused attention: ctx = softmax(q k^T + bias) v, written as [B,S,D]
    flash_attn_kernel<<<dim3(SS / 64, BH), 256, FA_SMEM_BYTES>>>(
        q, k, v, bias, ctx);

    // 6. y = x + ctx @ Wo^T
    sgemm_nt<<<g512, 256>>>(ctx, Wo, y, x, DD, DD, DD, DD, 2);

    // 7. h2 = rmsnorm(y) * g2
    rmsnorm_kernel<<<ROWS, 128>>>(y, gm2, h2);

    // 8. ff = relu(h2 @ wi^T)   (M=8192, N=2048, K=512)
    sgemm_nt<<<dim3(DFF / 128, ROWS / 128), 256>>>(h2, wi, ff, nullptr, DD, DD, DD, DFF, 1);

    // 9. out = y + ff @ wo^T    (M=8192, N=512, K=2048)
    sgemm_nt<<<g512, 256>>>(ff, wo, out, y, DFF, DFF, DFF, DD, 2);
}

// round 5
// speedup vs baseline: 1.7768x; 1.7768x over previous
#include <cuda_runtime.h>
#include <cuda_bf16.h>
#include <cstdint>

// Problem constants
#define BB   8
#define SS   1024
#define DD   512
#define HH   8
#define HDQ  64
#define DFF  2048
#define ROWS (BB*SS)          // 8192
#define BH   (BB*HH)          // 64

// ---------------- scratch (static __device__ arrays; no allocation APIs) ----
__device__ float g_h  [ROWS*DD];
__device__ float g_q  [ROWS*DD];
__device__ float g_k  [ROWS*DD];
__device__ float g_v  [ROWS*DD];
__device__ float g_ctx[ROWS*DD];
__device__ float g_y  [ROWS*DD];
__device__ float g_h2 [ROWS*DD];
__device__ float g_ff [ROWS*DFF];

// ---------------------------------------------------------------- helpers ---
__device__ __forceinline__ unsigned f2tf32(float f) {
    unsigned r;
    asm("cvt.rna.tf32.f32 %0, %1;" : "=r"(r) : "f"(f));
    return r;
}

__device__ __forceinline__ void mma_tf32(float c[4],
    unsigned a0, unsigned a1, unsigned a2, unsigned a3,
    unsigned b0, unsigned b1)
{
    asm volatile(
        "mma.sync.aligned.m16n8k8.row.col.f32.tf32.tf32.f32 "
        "{%0,%1,%2,%3}, {%4,%5,%6,%7}, {%8,%9}, {%0,%1,%2,%3};"
        : "+f"(c[0]), "+f"(c[1]), "+f"(c[2]), "+f"(c[3])
        : "r"(a0), "r"(a1), "r"(a2), "r"(a3), "r"(b0), "r"(b1));
}

// ---------------------------------------------------------------- rmsnorm ---
// one block per row of 512; 128 threads x float4
__global__ void __launch_bounds__(128) rmsnorm_kernel(
    const float* __restrict__ x, const float* __restrict__ w,
    float* __restrict__ out)
{
    const int row = blockIdx.x;
    const int tid = threadIdx.x;
    const float4 v = reinterpret_cast<const float4*>(x + (size_t)row * DD)[tid];
    float ss = v.x*v.x + v.y*v.y + v.z*v.z + v.w*v.w;

    __shared__ float red[4];
    #pragma unroll
    for (int o = 16; o; o >>= 1) ss += __shfl_xor_sync(0xffffffffu, ss, o);
    if ((tid & 31) == 0) red[tid >> 5] = ss;
    __syncthreads();
    if (tid < 32) {
        float t = 0.f;
        if (tid < 4) t = red[tid];
        t += __shfl_xor_sync(0xffffffffu, t, 1);
        t += __shfl_xor_sync(0xffffffffu, t, 2);
        if (tid == 0) red[0] = t;
    }
    __syncthreads();
    const float tot = red[0];

    const float r = rsqrtf(tot * (1.0f / DD) + 1e-6f);
    const float4 g = reinterpret_cast<const float4*>(w)[tid];
    float4 o;
    o.x = v.x * g.x * r; o.y = v.y * g.y * r;
    o.z = v.z * g.z * r; o.w = v.w * g.w * r;
    reinterpret_cast<float4*>(out + (size_t)row * DD)[tid] = o;
}

// ----------------------------------------------------- tf32 tensor GEMM NT --
// C[M,N] = A[M,K] * B[N,K]^T (+epilogue). tf32 mma.sync m16n8k8, fp32 accum.
// 128x128 CTA tile, K-step 16, 256 threads = 8 warps of 64x32 warp tiles.
// Shared stride 20 floats -> conflict-free fragment LDS.
// epi: 0 = plain, 1 = relu, 2 = residual add (C = R + A*B^T)
__global__ void __launch_bounds__(256, 2) tgemm_nt(
    const float* __restrict__ A, const float* __restrict__ B,
    float* __restrict__ C, const float* __restrict__ R,
    int K, int lda, int ldb, int ldc, int epi)
{
    __shared__ unsigned As[128 * 20];
    __shared__ unsigned Bs[128 * 20];
    const int tid  = threadIdx.x;
    const int lane = tid & 31;
    const int wid  = tid >> 5;
    const int wm   = (wid & 1) * 64;   // warp m-offset within CTA tile
    const int wn   = (wid >> 1) * 32;  // warp n-offset
    const int m0 = blockIdx.y * 128, n0 = blockIdx.x * 128;

    // global-load mapping: 512 float4 slots per matrix, thread t -> slots t, t+256
    const int gr0 = tid >> 2;          // rows 0..63
    const int gr1 = gr0 + 64;          // rows 64..127
    const int gc  = (tid & 3) * 4;     // k-column within 16-wide stage

    const float* Ag0 = A + (size_t)(m0 + gr0) * lda + gc;
    const float* Ag1 = A + (size_t)(m0 + gr1) * lda + gc;
    const float* Bg0 = B + (size_t)(n0 + gr0) * ldb + gc;
    const float* Bg1 = B + (size_t)(n0 + gr1) * ldb + gc;

    float acc[4][4][4];
    #pragma unroll
    for (int mi = 0; mi < 4; ++mi)
        #pragma unroll
        for (int ni = 0; ni < 4; ++ni)
            #pragma unroll
            for (int j = 0; j < 4; ++j) acc[mi][ni][j] = 0.f;

    const int fr = lane >> 2, fc = lane & 3;

    for (int k0 = 0; k0 < K; k0 += 16) {
        const float4 a0 = *reinterpret_cast<const float4*>(Ag0 + k0);
        const float4 a1 = *reinterpret_cast<const float4*>(Ag1 + k0);
        const float4 b0 = *reinterpret_cast<const float4*>(Bg0 + k0);
        const float4 b1 = *reinterpret_cast<const float4*>(Bg1 + k0);
        __syncthreads();
        {
            unsigned* pa0 = &As[gr0 * 20 + gc];
            pa0[0] = f2tf32(a0.x); pa0[1] = f2tf32(a0.y);
            pa0[2] = f2tf32(a0.z); pa0[3] = f2tf32(a0.w);
            unsigned* pa1 = &As[gr1 * 20 + gc];
            pa1[0] = f2tf32(a1.x); pa1[1] = f2tf32(a1.y);
            pa1[2] = f2tf32(a1.z); pa1[3] = f2tf32(a1.w);
            unsigned* pb0 = &Bs[gr0 * 20 + gc];
            pb0[0] = f2tf32(b0.x); pb0[1] = f2tf32(b0.y);
            pb0[2] = f2tf32(b0.z); pb0[3] = f2tf32(b0.w);
            unsigned* pb1 = &Bs[gr1 * 20 + gc];
            pb1[0] = f2tf32(b1.x); pb1[1] = f2tf32(b1.y);
            pb1[2] = f2tf32(b1.z); pb1[3] = f2tf32(b1.w);
        }
        __syncthreads();

        #pragma unroll
        for (int kk = 0; kk < 16; kk += 8) {
            unsigned af[4][4], bf[4][2];
            #pragma unroll
            for (int mi = 0; mi < 4; ++mi) {
                const unsigned* p = &As[(wm + mi * 16 + fr) * 20 + kk + fc];
                af[mi][0] = p[0];
                af[mi][1] = p[8 * 20];
                af[mi][2] = p[4];
                af[mi][3] = p[8 * 20 + 4];
            }
            #pragma unroll
            for (int ni = 0; ni < 4; ++ni) {
                const unsigned* p = &Bs[(wn + ni * 8 + fr) * 20 + kk + fc];
                bf[ni][0] = p[0];
                bf[ni][1] = p[4];
            }
            #pragma unroll
            for (int mi = 0; mi < 4; ++mi)
                #pragma unroll
                for (int ni = 0; ni < 4; ++ni)
                    mma_tf32(acc[mi][ni],
                             af[mi][0], af[mi][1], af[mi][2], af[mi][3],
                             bf[ni][0], bf[ni][1]);
        }
    }

    // epilogue: c0/c1 -> (row, col..col+1), c2/c3 -> (row+8, col..col+1)
    #pragma unroll
    for (int mi = 0; mi < 4; ++mi) {
        const int row = m0 + wm + mi * 16 + (lane >> 2);
        #pragma unroll
        for (int ni = 0; ni < 4; ++ni) {
            const int col = n0 + wn + ni * 8 + (lane & 3) * 2;
            const size_t i0 = (size_t)row * ldc + col;
            const size_t i1 = (size_t)(row + 8) * ldc + col;
            float2 v0 = make_float2(acc[mi][ni][0], acc[mi][ni][1]);
            float2 v1 = make_float2(acc[mi][ni][2], acc[mi][ni][3]);
            if (epi == 1) {
                v0.x = fmaxf(v0.x, 0.f); v0.y = fmaxf(v0.y, 0.f);
                v1.x = fmaxf(v1.x, 0.f); v1.y = fmaxf(v1.y, 0.f);
            } else if (epi == 2) {
                const float2 r0 = *reinterpret_cast<const float2*>(R + i0);
                const float2 r1 = *reinterpret_cast<const float2*>(R + i1);
                v0.x += r0.x; v0.y += r0.y;
                v1.x += r1.x; v1.y += r1.y;
            }
            *reinterpret_cast<float2*>(C + i0) = v0;
            *reinterpret_cast<float2*>(C + i1) = v1;
        }
    }
}

// ------------------------------------------------------- fused attention ----
// Flash-style: per CTA one (bh, 64-row q-tile). Online softmax over K-tiles
// of 64. Bias added to raw scores (T5: no 1/sqrt(d)).
#define FA_SMEM_BYTES 67584

__global__ void __launch_bounds__(256, 2) flash_attn_kernel(
    const float* __restrict__ Q, const float* __restrict__ Kg,
    const float* __restrict__ V, const float* __restrict__ bias,
    float* __restrict__ O)
{
    extern __shared__ float smem[];
    float (*Qst)[68] = reinterpret_cast<float(*)[68]>(smem);
    float (*Kst)[68] = reinterpret_cast<float(*)[68]>(smem + 17408/4);
    float (*Vs )[64] = reinterpret_cast<float(*)[64]>(smem + 34816/4);
    float (*Ps )[64] = reinterpret_cast<float(*)[64]>(smem + 51200/4);

    const int tid = threadIdx.x;
    const int tx = tid & 15, ty = tid >> 4;
    const int q0 = blockIdx.x * 64;
    const int bh = blockIdx.y;
    const int b = bh >> 3, h = bh & 7;

    const float* Qb = Q  + (size_t)b * SS * DD + h * HDQ;
    const float* Kb = Kg + (size_t)b * SS * DD + h * HDQ;
    const float* Vb = V  + (size_t)b * SS * DD + h * HDQ;
    const float* Bb = bias + (size_t)bh * SS * SS;

    #pragma unroll
    for (int t = 0; t < 4; ++t) {
        const int idx = tid + t * 256;
        const int row = idx >> 4;
        const int dv  = idx & 15;
        const float4 qv = *reinterpret_cast<const float4*>(
            Qb + (size_t)(q0 + row) * DD + dv * 4);
        Qst[dv*4+0][row] = qv.x; Qst[dv*4+1][row] = qv.y;
        Qst[dv*4+2][row] = qv.z; Qst[dv*4+3][row] = qv.w;
    }

    float o[4][4];
    float m[4], l[4];
    #pragma unroll
    for (int i = 0; i < 4; ++i) {
        m[i] = -3.4e38f; l[i] = 0.f;
        #pragma unroll
        for (int j = 0; j < 4; ++j) o[i][j] = 0.f;
    }
    __syncthreads();

    for (int k0 = 0; k0 < SS; k0 += 64) {
        float4 kreg[4], vreg[4];
        #pragma unroll
        for (int t = 0; t < 4; ++t) {
            const int idx = tid + t * 256;
            const int row = idx >> 4, dv = idx & 15;
            kreg[t] = *reinterpret_cast<const float4*>(
                Kb + (size_t)(k0 + row) * DD + dv * 4);
            vreg[t] = *reinterpret_cast<const float4*>(
                Vb + (size_t)(k0 + row) * DD + dv * 4);
        }
        __syncthreads();
        #pragma unroll
        for (int t = 0; t < 4; ++t) {
            const int idx = tid + t * 256;
            const int row = idx >> 4, dv = idx & 15;
            Kst[dv*4+0][row] = kreg[t].x; Kst[dv*4+1][row] = kreg[t].y;
            Kst[dv*4+2][row] = kreg[t].z; Kst[dv*4+3][row] = kreg[t].w;
            *reinterpret_cast<float4*>(&Vs[row][dv*4]) = vreg[t];
        }
        __syncthreads();

        float s[4][4];
        #pragma unroll
        for (int i = 0; i < 4; ++i) {
            const float4 bv = *reinterpret_cast<const float4*>(
                Bb + (size_t)(q0 + ty*4 + i) * SS + k0 + tx*4);
            s[i][0] = bv.x; s[i][1] = bv.y; s[i][2] = bv.z; s[i][3] = bv.w;
        }
        #pragma unroll
        for (int kk = 0; kk < 64; ++kk) {
            const float4 qv = *reinterpret_cast<const float4*>(&Qst[kk][ty*4]);
            const float4 kv = *reinterpret_cast<const float4*>(&Kst[kk][tx*4]);
            const float qa[4] = {qv.x, qv.y, qv.z, qv.w};
            const float ka[4] = {kv.x, kv.y, kv.z, kv.w};
            #pragma unroll
            for (int i = 0; i < 4; ++i)
                #pragma unroll
                for (int j = 0; j < 4; ++j)
                    s[i][j] += qa[i] * ka[j];
        }

        #pragma unroll
        for (int i = 0; i < 4; ++i) {
            float tm = fmaxf(fmaxf(s[i][0], s[i][1]), fmaxf(s[i][2], s[i][3]));
            #pragma unroll
            for (int off = 1; off < 16; off <<= 1)
                tm = fmaxf(tm, __shfl_xor_sync(0xffffffffu, tm, off, 16));
            const float mn = fmaxf(m[i], tm);
            const float scale = __expf(m[i] - mn);
            m[i] = mn;
            float rs = 0.f;
            #pragma unroll
            for (int j = 0; j < 4; ++j) {
                s[i][j] = __expf(s[i][j] - mn);
                rs += s[i][j];
            }
            #pragma unroll
            for (int off = 1; off < 16; off <<= 1)
                rs += __shfl_xor_sync(0xffffffffu, rs, off, 16);
            l[i] = l[i] * scale + rs;
            #pragma unroll
            for (int j = 0; j < 4; ++j) o[i][j] *= scale;
            *reinterpret_cast<float4*>(&Ps[ty*4 + i][tx*4]) =
                make_float4(s[i][0], s[i][1], s[i][2], s[i][3]);
        }
        __syncthreads();

        #pragma unroll
        for (int kk = 0; kk < 64; kk += 4) {
            float4 pr[4];
            #pragma unroll
            for (int i = 0; i < 4; ++i)
                pr[i] = *reinterpret_cast<const float4*>(&Ps[ty*4 + i][kk]);
            #pragma unroll
            for (int t = 0; t < 4; ++t) {
                const float4 vv = *reinterpret_cast<const float4*>(&Vs[kk + t][tx*4]);
                const float pw[4] = {
                    t == 0 ? pr[0].x : t == 1 ? pr[0].y : t == 2 ? pr[0].z : pr[0].w,
                    t == 0 ? pr[1].x : t == 1 ? pr[1].y : t == 2 ? pr[1].z : pr[1].w,
                    t == 0 ? pr[2].x : t == 1 ? pr[2].y : t == 2 ? pr[2].z : pr[2].w,
                    t == 0 ? pr[3].x : t == 1 ? pr[3].y : t == 2 ? pr[3].z : pr[3].w };
                #pragma unroll
                for (int i = 0; i < 4; ++i) {
                    o[i][0] += pw[i] * vv.x;
                    o[i][1] += pw[i] * vv.y;
                    o[i][2] += pw[i] * vv.z;
                    o[i][3] += pw[i] * vv.w;
                }
            }
        }
        __syncthreads();
    }

    #pragma unroll
    for (int i = 0; i < 4; ++i) {
        const float inv = 1.0f / l[i];
        float* op = O + (size_t)b * SS * DD + (size_t)(q0 + ty*4 + i) * DD
                      + h * HDQ + tx * 4;
        *reinterpret_cast<float4*>(op) =
            make_float4(o[i][0]*inv, o[i][1]*inv, o[i][2]*inv, o[i][3]*inv);
    }
}

// ------------------------------------------------------------------ host ----
extern "C" void kernel_launch(void* const* d_in, const int* in_sizes, int n_in,
                              void* d_out, int out_size)
{
    const float* Wk   = (const float*)d_in[0];
    const float* Wo   = (const float*)d_in[1];
    const float* Wq   = (const float*)d_in[2];
    const float* Wv   = (const float*)d_in[3];
    const float* gm1  = (const float*)d_in[4];
    const float* wi   = (const float*)d_in[5];
    const float* wo   = (const float*)d_in[6];
    const float* gm2  = (const float*)d_in[7];
    const float* x    = (const float*)d_in[8];
    const float* bias = (const float*)d_in[9];
    float* out = (float*)d_out;

    float *h, *q, *k, *v, *ctx, *y, *h2, *ff;
    cudaGetSymbolAddress((void**)&h,   g_h);
    cudaGetSymbolAddress((void**)&q,   g_q);
    cudaGetSymbolAddress((void**)&k,   g_k);
    cudaGetSymbolAddress((void**)&v,   g_v);
    cudaGetSymbolAddress((void**)&ctx, g_ctx);
    cudaGetSymbolAddress((void**)&y,   g_y);
    cudaGetSymbolAddress((void**)&h2,  g_h2);
    cudaGetSymbolAddress((void**)&ff,  g_ff);

    cudaFuncSetAttribute(flash_attn_kernel,
                         cudaFuncAttributeMaxDynamicSharedMemorySize,
                         FA_SMEM_BYTES);

    // 1. h = rmsnorm(x) * g1
    rmsnorm_kernel<<<ROWS, 128>>>(x, gm1, h);

    // 2-4. q/k/v = h @ W^T      (M=8192, N=512, K=512)
    const dim3 g512(DD / 128, ROWS / 128);
    tgemm_nt<<<g512, 256>>>(h, Wq, q, nullptr, DD, DD, DD, DD, 0);
    tgemm_nt<<<g512, 256>>>(h, Wk, k, nullptr, DD, DD, DD, DD, 0);
    tgemm_nt<<<g512, 256>>>(h, Wv, v, nullptr, DD, DD, DD, DD, 0);

    // 5. fused attention: ctx = softmax(q k^T + bias) v, written as [B,S,D]
    flash_attn_kernel<<<dim3(SS / 64, BH), 256, FA_SMEM_BYTES>>>(
        q, k, v, bias, ctx);

    // 6. y = x + ctx @ Wo^T
    tgemm_nt<<<g512, 256>>>(ctx, Wo, y, x, DD, DD, DD, DD, 2);

    // 7. h2 = rmsnorm(y) * g2
    rmsnorm_kernel<<<ROWS, 128>>>(y, gm2, h2);

    // 8. ff = relu(h2 @ wi^T)   (M=8192, N=2048, K=512)
    tgemm_nt<<<dim3(DFF / 128, ROWS / 128), 256>>>(h2, wi, ff, nullptr, DD, DD, DD, DFF, 1);

    // 9. out = y + ff @ wo^T    (M=8192, N=512, K=2048)
    tgemm_nt<<<g512, 256>>>(ff, wo, out, y, DFF, DFF, DFF, DD, 2);
}

// round 7
// speedup vs baseline: 2.6417x; 1.4868x over previous
#include <cuda_runtime.h>
#include <cuda_bf16.h>
#include <cstdint>

// Problem constants
#define BB   8
#define SS   1024
#define DD   512
#define HH   8
#define HDQ  64
#define DFF  2048
#define ROWS (BB*SS)          // 8192
#define BH   (BB*HH)          // 64

// ---------------- scratch (static __device__ arrays; no allocation APIs) ----
__device__ float g_h  [ROWS*DD];
__device__ float g_q  [ROWS*DD];
__device__ float g_k  [ROWS*DD];
__device__ float g_v  [ROWS*DD];
__device__ float g_ctx[ROWS*DD];
__device__ float g_y  [ROWS*DD];
__device__ float g_h2 [ROWS*DD];
__device__ float g_ff [ROWS*DFF];

// ---------------------------------------------------------------- helpers ---
__device__ __forceinline__ void mma_tf32(float c[4],
    unsigned a0, unsigned a1, unsigned a2, unsigned a3,
    unsigned b0, unsigned b1)
{
    asm volatile(
        "mma.sync.aligned.m16n8k8.row.col.f32.tf32.tf32.f32 "
        "{%0,%1,%2,%3}, {%4,%5,%6,%7}, {%8,%9}, {%0,%1,%2,%3};"
        : "+f"(c[0]), "+f"(c[1]), "+f"(c[2]), "+f"(c[3])
        : "r"(a0), "r"(a1), "r"(a2), "r"(a3), "r"(b0), "r"(b1));
}

__device__ __forceinline__ void cp16(void* smem_ptr, const void* gmem_ptr) {
    unsigned s = (unsigned)__cvta_generic_to_shared(smem_ptr);
    asm volatile("cp.async.cg.shared.global [%0], [%1], 16;"
                 :: "r"(s), "l"(gmem_ptr));
}

// ---------------------------------------------------------------- rmsnorm ---
__global__ void __launch_bounds__(128) rmsnorm_kernel(
    const float* __restrict__ x, const float* __restrict__ w,
    float* __restrict__ out)
{
    const int row = blockIdx.x;
    const int tid = threadIdx.x;
    const float4 v = reinterpret_cast<const float4*>(x + (size_t)row * DD)[tid];
    float ss = v.x*v.x + v.y*v.y + v.z*v.z + v.w*v.w;

    __shared__ float red[4];
    #pragma unroll
    for (int o = 16; o; o >>= 1) ss += __shfl_xor_sync(0xffffffffu, ss, o);
    if ((tid & 31) == 0) red[tid >> 5] = ss;
    __syncthreads();
    if (tid < 32) {
        float t = 0.f;
        if (tid < 4) t = red[tid];
        t += __shfl_xor_sync(0xffffffffu, t, 1);
        t += __shfl_xor_sync(0xffffffffu, t, 2);
        if (tid == 0) red[0] = t;
    }
    __syncthreads();
    const float tot = red[0];

    const float r = rsqrtf(tot * (1.0f / DD) + 1e-6f);
    const float4 g = reinterpret_cast<const float4*>(w)[tid];
    float4 o;
    o.x = v.x * g.x * r; o.y = v.y * g.y * r;
    o.z = v.z * g.z * r; o.w = v.w * g.w * r;
    reinterpret_cast<float4*>(out + (size_t)row * DD)[tid] = o;
}

// ------------------------------------- tf32 tensor GEMM NT, double-buffered -
// C[M,N] = A[M,K] * B[N,K]^T (+epilogue). Raw fp32 bits fed to tf32 mma
// (HW truncates mantissa). cp.async 2-stage pipeline hides global latency.
// epi: 0 = plain, 1 = relu, 2 = residual add (C = R + A*B^T)
__global__ void __launch_bounds__(256, 2) tgemm_nt(
    const float* __restrict__ A, const float* __restrict__ B,
    float* __restrict__ C, const float* __restrict__ R,
    int K, int lda, int ldb, int ldc, int epi)
{
    __shared__ unsigned As[2][128 * 20];
    __shared__ unsigned Bs[2][128 * 20];
    const int tid  = threadIdx.x;
    const int lane = tid & 31;
    const int wid  = tid >> 5;
    const int wm   = (wid & 1) * 64;
    const int wn   = (wid >> 1) * 32;
    const int m0 = blockIdx.y * 128, n0 = blockIdx.x * 128;

    const int gr0 = tid >> 2;          // rows 0..63
    const int gr1 = gr0 + 64;          // rows 64..127
    const int gc  = (tid & 3) * 4;     // k-col within 16-wide stage

    const float* Ag0 = A + (size_t)(m0 + gr0) * lda + gc;
    const float* Ag1 = A + (size_t)(m0 + gr1) * lda + gc;
    const float* Bg0 = B + (size_t)(n0 + gr0) * ldb + gc;
    const float* Bg1 = B + (size_t)(n0 + gr1) * ldb + gc;

    float acc[4][4][4];
    #pragma unroll
    for (int mi = 0; mi < 4; ++mi)
        #pragma unroll
        for (int ni = 0; ni < 4; ++ni)
            #pragma unroll
            for (int j = 0; j < 4; ++j) acc[mi][ni][j] = 0.f;

    const int fr = lane >> 2, fc = lane & 3;
    const int nit = K >> 4;

    // prologue: stage 0
    cp16(&As[0][gr0 * 20 + gc], Ag0);
    cp16(&As[0][gr1 * 20 + gc], Ag1);
    cp16(&Bs[0][gr0 * 20 + gc], Bg0);
    cp16(&Bs[0][gr1 * 20 + gc], Bg1);
    asm volatile("cp.async.commit_group;");

    for (int it = 0; it < nit; ++it) {
        const int cur = it & 1;
        if (it + 1 < nit) {
            const int nk = (it + 1) << 4;
            cp16(&As[cur ^ 1][gr0 * 20 + gc], Ag0 + nk);
            cp16(&As[cur ^ 1][gr1 * 20 + gc], Ag1 + nk);
            cp16(&Bs[cur ^ 1][gr0 * 20 + gc], Bg0 + nk);
            cp16(&Bs[cur ^ 1][gr1 * 20 + gc], Bg1 + nk);
            asm volatile("cp.async.commit_group;");
            asm volatile("cp.async.wait_group 1;");
        } else {
            asm volatile("cp.async.wait_group 0;");
        }
        __syncthreads();

        const unsigned* as = As[cur];
        const unsigned* bs = Bs[cur];
        #pragma unroll
        for (int kk = 0; kk < 16; kk += 8) {
            unsigned af[4][4], bf[4][2];
            #pragma unroll
            for (int mi = 0; mi < 4; ++mi) {
                const unsigned* p = &as[(wm + mi * 16 + fr) * 20 + kk + fc];
                af[mi][0] = p[0];
                af[mi][1] = p[8 * 20];
                af[mi][2] = p[4];
                af[mi][3] = p[8 * 20 + 4];
            }
            #pragma unroll
            for (int ni = 0; ni < 4; ++ni) {
                const unsigned* p = &bs[(wn + ni * 8 + fr) * 20 + kk + fc];
                bf[ni][0] = p[0];
                bf[ni][1] = p[4];
            }
            #pragma unroll
            for (int mi = 0; mi < 4; ++mi)
                #pragma unroll
                for (int ni = 0; ni < 4; ++ni)
                    mma_tf32(acc[mi][ni],
                             af[mi][0], af[mi][1], af[mi][2], af[mi][3],
                             bf[ni][0], bf[ni][1]);
        }
        __syncthreads();   // protect stage reuse at it+2
    }

    #pragma unroll
    for (int mi = 0; mi < 4; ++mi) {
        const int row = m0 + wm + mi * 16 + (lane >> 2);
        #pragma unroll
        for (int ni = 0; ni < 4; ++ni) {
            const int col = n0 + wn + ni * 8 + (lane & 3) * 2;
            const size_t i0 = (size_t)row * ldc + col;
            const size_t i1 = (size_t)(row + 8) * ldc + col;
            float2 v0 = make_float2(acc[mi][ni][0], acc[mi][ni][1]);
            float2 v1 = make_float2(acc[mi][ni][2], acc[mi][ni][3]);
            if (epi == 1) {
                v0.x = fmaxf(v0.x, 0.f); v0.y = fmaxf(v0.y, 0.f);
                v1.x = fmaxf(v1.x, 0.f); v1.y = fmaxf(v1.y, 0.f);
            } else if (epi == 2) {
                const float2 r0 = *reinterpret_cast<const float2*>(R + i0);
                const float2 r1 = *reinterpret_cast<const float2*>(R + i1);
                v0.x += r0.x; v0.y += r0.y;
                v1.x += r1.x; v1.y += r1.y;
            }
            *reinterpret_cast<float2*>(C + i0) = v0;
            *reinterpret_cast<float2*>(C + i1) = v1;
        }
    }
}

// ----------------------------------------------- tf32 tensor flash attention
// 128 q-rows x 64 k-cols per tile, 8 warps, online softmax on mma fragments.
// smem: Qsm[128][68] | Ks[64][68] | Vs[64][72] | Ps[128][68] (bias staging + P)
#define FA_SMEM_BYTES 105472

__global__ void __launch_bounds__(256, 2) flash_tf32_kernel(
    const float* __restrict__ Q, const float* __restrict__ Kg,
    const float* __restrict__ V, const float* __restrict__ bias,
    float* __restrict__ O)
{
    extern __shared__ float sm[];
    float* Qsm = sm;                          // [128][68]
    float* Ks  = sm + 8704;                   // [64][68]
    float* Vs  = sm + 8704 + 4352;            // [64][72]
    float* Ps  = sm + 8704 + 4352 + 4608;     // [128][68]

    const int tid = threadIdx.x, lane = tid & 31, w = tid >> 5;
    const int fr = lane >> 2, fc = lane & 3;
    const int q0 = blockIdx.x * 128;
    const int bh = blockIdx.y;
    const int b = bh >> 3, h = bh & 7;

    const float* Qb = Q  + (size_t)b * SS * DD + h * HDQ;
    const float* Kb = Kg + (size_t)b * SS * DD + h * HDQ;
    const float* Vb = V  + (size_t)b * SS * DD + h * HDQ;
    const float* Bb = bias + (size_t)bh * SS * SS;

    const int rlo = 16 * w + fr;
    const int rhi = rlo + 8;

    // ---- stage Q [128][64] -> Qsm, coalesced ----
    #pragma unroll
    for (int t = 0; t < 8; ++t) {
        const int idx = tid + t * 256;        // 0..2047 float4 slots
        const int row = idx >> 4, c4 = idx & 15;
        const float4 qv = *reinterpret_cast<const float4*>(
            Qb + (size_t)(q0 + row) * DD + c4 * 4);
        *reinterpret_cast<float4*>(&Qsm[row * 68 + c4 * 4]) = qv;
    }
    __syncthreads();

    float Ox[8][4];
    #pragma unroll
    for (int d = 0; d < 8; ++d)
        #pragma unroll
        for (int j = 0; j < 4; ++j) Ox[d][j] = 0.f;
    float m0 = -3.4e38f, m1 = -3.4e38f, l0 = 0.f, l1 = 0.f;

    for (int k0 = 0; k0 < SS; k0 += 64) {
        // ---- K,V global -> regs (coalesced) ----
        float4 kr[4], vr[4];
        #pragma unroll
        for (int t = 0; t < 4; ++t) {
            const int idx = tid + t * 256;    // 0..1023
            const int row = idx >> 4, c4 = idx & 15;
            kr[t] = *reinterpret_cast<const float4*>(
                Kb + (size_t)(k0 + row) * DD + c4 * 4);
            vr[t] = *reinterpret_cast<const float4*>(
                Vb + (size_t)(k0 + row) * DD + c4 * 4);
        }
        __syncthreads();   // previous tile PV (Ps, Vs reads) complete
        #pragma unroll
        for (int t = 0; t < 4; ++t) {
            const int idx = tid + t * 256;
            const int row = idx >> 4, c4 = idx & 15;
            *reinterpret_cast<float4*>(&Ks[row * 68 + c4 * 4]) = kr[t];
            *reinterpret_cast<float4*>(&Vs[row * 72 + c4 * 4]) = vr[t];
        }
        // ---- stage bias tile [128][64] -> Ps (coalesced) ----
        #pragma unroll
        for (int t = 0; t < 8; ++t) {
            const int idx = tid + t * 256;
            const int row = idx >> 4, c4 = idx & 15;
            const float4 bv = *reinterpret_cast<const float4*>(
                Bb + (size_t)(q0 + row) * SS + k0 + c4 * 4);
            *reinterpret_cast<float4*>(&Ps[row * 68 + c4 * 4]) = bv;
        }
        __syncthreads();

        // ---- S = bias; S += Q K^T ----
        float Sx[8][4];
        #pragma unroll
        for (int nb = 0; nb < 8; ++nb) {
            const float2 blo = *reinterpret_cast<const float2*>(
                &Ps[rlo * 68 + 8 * nb + 2 * fc]);
            const float2 bhi = *reinterpret_cast<const float2*>(
                &Ps[rhi * 68 + 8 * nb + 2 * fc]);
            Sx[nb][0] = blo.x; Sx[nb][1] = blo.y;
            Sx[nb][2] = bhi.x; Sx[nb][3] = bhi.y;
        }
        #pragma unroll
        for (int kb = 0; kb < 8; ++kb) {
            const unsigned a0 = __float_as_uint(Qsm[rlo * 68 + 8 * kb + fc]);
            const unsigned a1 = __float_as_uint(Qsm[rhi * 68 + 8 * kb + fc]);
            const unsigned a2 = __float_as_uint(Qsm[rlo * 68 + 8 * kb + fc + 4]);
            const unsigned a3 = __float_as_uint(Qsm[rhi * 68 + 8 * kb + fc + 4]);
            #pragma unroll
            for (int nb = 0; nb < 8; ++nb) {
                const unsigned b0 = __float_as_uint(Ks[(8 * nb + fr) * 68 + 8 * kb + fc]);
                const unsigned b1 = __float_as_uint(Ks[(8 * nb + fr) * 68 + 8 * kb + fc + 4]);
                mma_tf32(Sx[nb], a0, a1, a2, a3, b0, b1);
            }
        }

        // ---- online softmax (rows rlo via c0,c1 ; rows rhi via c2,c3) ----
        float mxlo = -3.4e38f, mxhi = -3.4e38f;
        #pragma unroll
        for (int nb = 0; nb < 8; ++nb) {
            mxlo = fmaxf(mxlo, fmaxf(Sx[nb][0], Sx[nb][1]));
            mxhi = fmaxf(mxhi, fmaxf(Sx[nb][2], Sx[nb][3]));
        }
        mxlo = fmaxf(mxlo, __shfl_xor_sync(0xffffffffu, mxlo, 1));
        mxlo = fmaxf(mxlo, __shfl_xor_sync(0xffffffffu, mxlo, 2));
        mxhi = fmaxf(mxhi, __shfl_xor_sync(0xffffffffu, mxhi, 1));
        mxhi = fmaxf(mxhi, __shfl_xor_sync(0xffffffffu, mxhi, 2));
        const float Mlo = fmaxf(m0, mxlo), Mhi = fmaxf(m1, mxhi);
        const float sclo = __expf(m0 - Mlo), schi = __expf(m1 - Mhi);
        m0 = Mlo; m1 = Mhi;
        float slo = 0.f, shi = 0.f;
        #pragma unroll
        for (int nb = 0; nb < 8; ++nb) {
            Sx[nb][0] = __expf(Sx[nb][0] - Mlo);
            Sx[nb][1] = __expf(Sx[nb][1] - Mlo);
            Sx[nb][2] = __expf(Sx[nb][2] - Mhi);
            Sx[nb][3] = __expf(Sx[nb][3] - Mhi);
            slo += Sx[nb][0] + Sx[nb][1];
            shi += Sx[nb][2] + Sx[nb][3];
        }
        slo += __shfl_xor_sync(0xffffffffu, slo, 1);
        slo += __shfl_xor_sync(0xffffffffu, slo, 2);
        shi += __shfl_xor_sync(0xffffffffu, shi, 1);
        shi += __shfl_xor_sync(0xffffffffu, shi, 2);
        l0 = l0 * sclo + slo;
        l1 = l1 * schi + shi;
        #pragma unroll
        for (int d = 0; d < 8; ++d) {
            Ox[d][0] *= sclo; Ox[d][1] *= sclo;
            Ox[d][2] *= schi; Ox[d][3] *= schi;
        }
        // ---- write P (own-warp rows only) ----
        #pragma unroll
        for (int nb = 0; nb < 8; ++nb) {
            *reinterpret_cast<float2*>(&Ps[rlo * 68 + 8 * nb + 2 * fc]) =
                make_float2(Sx[nb][0], Sx[nb][1]);
            *reinterpret_cast<float2*>(&Ps[rhi * 68 + 8 * nb + 2 * fc]) =
                make_float2(Sx[nb][2], Sx[nb][3]);
        }
        __syncwarp();

        // ---- O += P V ----
        #pragma unroll
        for (int kb = 0; kb < 8; ++kb) {
            const unsigned p0 = __float_as_uint(Ps[rlo * 68 + 8 * kb + fc]);
            const unsigned p1 = __float_as_uint(Ps[rhi * 68 + 8 * kb + fc]);
            const unsigned p2 = __float_as_uint(Ps[rlo * 68 + 8 * kb + fc + 4]);
            const unsigned p3 = __float_as_uint(Ps[rhi * 68 + 8 * kb + fc + 4]);
            #pragma unroll
            for (int d = 0; d < 8; ++d) {
                const unsigned v0 = __float_as_uint(Vs[(8 * kb + fc) * 72 + 8 * d + fr]);
                const unsigned v1 = __float_as_uint(Vs[(8 * kb + fc + 4) * 72 + 8 * d + fr]);
                mma_tf32(Ox[d], p0, p1, p2, p3, v0, v1);
            }
        }
    }

    // ---- normalize + write ctx [B,S,D] ----
    const float il0 = 1.0f / l0, il1 = 1.0f / l1;
    float* Ob = O + (size_t)b * SS * DD + h * HDQ;
    #pragma unroll
    for (int d = 0; d < 8; ++d) {
        *reinterpret_cast<float2*>(
            Ob + (size_t)(q0 + rlo) * DD + 8 * d + 2 * fc) =
            make_float2(Ox[d][0] * il0, Ox[d][1] * il0);
        *reinterpret_cast<float2*>(
            Ob + (size_t)(q0 + rhi) * DD + 8 * d + 2 * fc) =
            make_float2(Ox[d][2] * il1, Ox[d][3] * il1);
    }
}

// ------------------------------------------------------------------ host ----
extern "C" void kernel_launch(void* const* d_in, const int* in_sizes, int n_in,
                              void* d_out, int out_size)
{
    const float* Wk   = (const float*)d_in[0];
    const float* Wo   = (const float*)d_in[1];
    const float* Wq   = (const float*)d_in[2];
    const float* Wv   = (const float*)d_in[3];
    const float* gm1  = (const float*)d_in[4];
    const float* wi   = (const float*)d_in[5];
    const float* wo   = (const float*)d_in[6];
    const float* gm2  = (const float*)d_in[7];
    const float* x    = (const float*)d_in[8];
    const float* bias = (const float*)d_in[9];
    float* out = (float*)d_out;

    float *h, *q, *k, *v, *ctx, *y, *h2, *ff;
    cudaGetSymbolAddress((void**)&h,   g_h);
    cudaGetSymbolAddress((void**)&q,   g_q);
    cudaGetSymbolAddress((void**)&k,   g_k);
    cudaGetSymbolAddress((void**)&v,   g_v);
    cudaGetSymbolAddress((void**)&ctx, g_ctx);
    cudaGetSymbolAddress((void**)&y,   g_y);
    cudaGetSymbolAddress((void**)&h2,  g_h2);
    cudaGetSymbolAddress((void**)&ff,  g_ff);

    cudaFuncSetAttribute(flash_tf32_kernel,
                         cudaFuncAttributeMaxDynamicSharedMemorySize,
                         FA_SMEM_BYTES);

    // 1. h = rmsnorm(x) * g1
    rmsnorm_kernel<<<ROWS, 128>>>(x, gm1, h);

    // 2-4. q/k/v = h @ W^T      (M=8192, N=512, K=512)
    const dim3 g512(DD / 128, ROWS / 128);
    tgemm_nt<<<g512, 256>>>(h, Wq, q, nullptr, DD, DD, DD, DD, 0);
    tgemm_nt<<<g512, 256>>>(h, Wk, k, nullptr, DD, DD, DD, DD, 0);
    tgemm_nt<<<g512, 256>>>(h, Wv, v, nullptr, DD, DD, DD, DD, 0);

    // 5. fused attention: ctx = softmax(q k^T + bias) v, written as [B,S,D]
    flash_tf32_kernel<<<dim3(SS / 128, BH), 256, FA_SMEM_BYTES>>>(
        q, k, v, bias, ctx);

    // 6. y = x + ctx @ Wo^T
    tgemm_nt<<<g512, 256>>>(ctx, Wo, y, x, DD, DD, DD, DD, 2);

    // 7. h2 = rmsnorm(y) * g2
    rmsnorm_kernel<<<ROWS, 128>>>(y, gm2, h2);

    // 8. ff = relu(h2 @ wi^T)   (M=8192, N=2048, K=512)
    tgemm_nt<<<dim3(DFF / 128, ROWS / 128), 256>>>(h2, wi, ff, nullptr, DD, DD, DD, DFF, 1);

    // 9. out = y + ff @ wo^T    (M=8192, N=512, K=2048)
    tgemm_nt<<<g512, 256>>>(ff, wo, out, y, DFF, DFF, DFF, DD, 2);
}

// round 8
// speedup vs baseline: 2.6889x; 1.0179x over previous
#include <cuda_runtime.h>
#include <cuda_bf16.h>
#include <cstdint>

// Problem constants
#define BB   8
#define SS   1024
#define DD   512
#define HH   8
#define HDQ  64
#define DFF  2048
#define ROWS (BB*SS)          // 8192
#define BH   (BB*HH)          // 64

#define GEMM_SMEM_BYTES 61440   // 3 stages x (As 10240 + Bs 10240)

// ---------------- scratch (static __device__ arrays; no allocation APIs) ----
__device__ float g_h  [ROWS*DD];
__device__ float g_q  [ROWS*DD];
__device__ float g_k  [ROWS*DD];
__device__ float g_v  [ROWS*DD];
__device__ float g_ctx[ROWS*DD];
__device__ float g_y  [ROWS*DD];
__device__ float g_h2 [ROWS*DD];
__device__ float g_ff [ROWS*DFF];

// ---------------------------------------------------------------- helpers ---
__device__ __forceinline__ void mma_tf32(float c[4],
    unsigned a0, unsigned a1, unsigned a2, unsigned a3,
    unsigned b0, unsigned b1)
{
    asm volatile(
        "mma.sync.aligned.m16n8k8.row.col.f32.tf32.tf32.f32 "
        "{%0,%1,%2,%3}, {%4,%5,%6,%7}, {%8,%9}, {%0,%1,%2,%3};"
        : "+f"(c[0]), "+f"(c[1]), "+f"(c[2]), "+f"(c[3])
        : "r"(a0), "r"(a1), "r"(a2), "r"(a3), "r"(b0), "r"(b1));
}

__device__ __forceinline__ void cp16(void* smem_ptr, const void* gmem_ptr) {
    unsigned s = (unsigned)__cvta_generic_to_shared(smem_ptr);
    asm volatile("cp.async.cg.shared.global [%0], [%1], 16;"
                 :: "r"(s), "l"(gmem_ptr));
}

// ---------------------------------------------------------------- rmsnorm ---
__global__ void __launch_bounds__(128) rmsnorm_kernel(
    const float* __restrict__ x, const float* __restrict__ w,
    float* __restrict__ out)
{
    const int row = blockIdx.x;
    const int tid = threadIdx.x;
    const float4 v = reinterpret_cast<const float4*>(x + (size_t)row * DD)[tid];
    float ss = v.x*v.x + v.y*v.y + v.z*v.z + v.w*v.w;

    __shared__ float red[4];
    #pragma unroll
    for (int o = 16; o; o >>= 1) ss += __shfl_xor_sync(0xffffffffu, ss, o);
    if ((tid & 31) == 0) red[tid >> 5] = ss;
    __syncthreads();
    if (tid < 32) {
        float t = 0.f;
        if (tid < 4) t = red[tid];
        t += __shfl_xor_sync(0xffffffffu, t, 1);
        t += __shfl_xor_sync(0xffffffffu, t, 2);
        if (tid == 0) red[0] = t;
    }
    __syncthreads();
    const float tot = red[0];

    const float r = rsqrtf(tot * (1.0f / DD) + 1e-6f);
    const float4 g = reinterpret_cast<const float4*>(w)[tid];
    float4 o;
    o.x = v.x * g.x * r; o.y = v.y * g.y * r;
    o.z = v.z * g.z * r; o.w = v.w * g.w * r;
    reinterpret_cast<float4*>(out + (size_t)row * DD)[tid] = o;
}

// --------------------------- tf32 tensor GEMM NT core, 3-stage cp.async -----
// C[M,N] = A[M,K] * B[N,K]^T (+epilogue). Raw fp32 bits fed to tf32 mma.
// 128x128 CTA tile, K-step 16, 8 warps (64x32 warp tiles), ONE sync/iter.
// epi: 0 = plain, 1 = relu, 2 = residual add (C = R + A*B^T)
__device__ __forceinline__ void tgemm_body(
    const float* __restrict__ A, const float* __restrict__ B,
    float* __restrict__ C, const float* __restrict__ R,
    int K, int lda, int ldb, int ldc, int epi, int m0, int n0,
    unsigned* sm)
{
    const int tid  = threadIdx.x;
    const int lane = tid & 31;
    const int wid  = tid >> 5;
    const int wm   = (wid & 1) * 64;
    const int wn   = (wid >> 1) * 32;

    const int gr0 = tid >> 2;          // rows 0..63
    const int gr1 = gr0 + 64;          // rows 64..127
    const int gc  = (tid & 3) * 4;     // k-col within 16-wide stage

    const float* Ag0 = A + (size_t)(m0 + gr0) * lda + gc;
    const float* Ag1 = A + (size_t)(m0 + gr1) * lda + gc;
    const float* Bg0 = B + (size_t)(n0 + gr0) * ldb + gc;
    const float* Bg1 = B + (size_t)(n0 + gr1) * ldb + gc;

    float acc[4][4][4];
    #pragma unroll
    for (int mi = 0; mi < 4; ++mi)
        #pragma unroll
        for (int ni = 0; ni < 4; ++ni)
            #pragma unroll
            for (int j = 0; j < 4; ++j) acc[mi][ni][j] = 0.f;

    const int fr = lane >> 2, fc = lane & 3;
    const int nit = K >> 4;

    // slot s: As at sm + s*2560, Bs at sm + 7680 + s*2560
    const int so0 = gr0 * 20 + gc, so1 = gr1 * 20 + gc;

    // prologue: stage 0 and 1
    #pragma unroll
    for (int s = 0; s < 2; ++s) {
        unsigned* as = sm + s * 2560;
        unsigned* bs = sm + 7680 + s * 2560;
        const int kk = s << 4;
        cp16(as + so0, Ag0 + kk);
        cp16(as + so1, Ag1 + kk);
        cp16(bs + so0, Bg0 + kk);
        cp16(bs + so1, Bg1 + kk);
        asm volatile("cp.async.commit_group;");
    }

    for (int it = 0; it < nit; ++it) {
        if (it + 1 < nit) asm volatile("cp.async.wait_group 1;");
        else              asm volatile("cp.async.wait_group 0;");
        __syncthreads();

        // prefetch stage it+2 into slot (it+2)%3 (computed at it-1; safe)
        if (it + 2 < nit) {
            const int s = (it + 2) % 3;
            unsigned* as = sm + s * 2560;
            unsigned* bs = sm + 7680 + s * 2560;
            const int kk = (it + 2) << 4;
            cp16(as + so0, Ag0 + kk);
            cp16(as + so1, Ag1 + kk);
            cp16(bs + so0, Bg0 + kk);
            cp16(bs + so1, Bg1 + kk);
            asm volatile("cp.async.commit_group;");
        }

        const int cs = it % 3;
        const unsigned* as = sm + cs * 2560;
        const unsigned* bs = sm + 7680 + cs * 2560;
        #pragma unroll
        for (int kk = 0; kk < 16; kk += 8) {
            unsigned af[4][4], bf[4][2];
            #pragma unroll
            for (int mi = 0; mi < 4; ++mi) {
                const unsigned* p = &as[(wm + mi * 16 + fr) * 20 + kk + fc];
                af[mi][0] = p[0];
                af[mi][1] = p[8 * 20];
                af[mi][2] = p[4];
                af[mi][3] = p[8 * 20 + 4];
            }
            #pragma unroll
            for (int ni = 0; ni < 4; ++ni) {
                const unsigned* p = &bs[(wn + ni * 8 + fr) * 20 + kk + fc];
                bf[ni][0] = p[0];
                bf[ni][1] = p[4];
            }
            #pragma unroll
            for (int mi = 0; mi < 4; ++mi)
                #pragma unroll
                for (int ni = 0; ni < 4; ++ni)
                    mma_tf32(acc[mi][ni],
                             af[mi][0], af[mi][1], af[mi][2], af[mi][3],
                             bf[ni][0], bf[ni][1]);
        }
    }

    #pragma unroll
    for (int mi = 0; mi < 4; ++mi) {
        const int row = m0 + wm + mi * 16 + (lane >> 2);
        #pragma unroll
        for (int ni = 0; ni < 4; ++ni) {
            const int col = n0 + wn + ni * 8 + (lane & 3) * 2;
            const size_t i0 = (size_t)row * ldc + col;
            const size_t i1 = (size_t)(row + 8) * ldc + col;
            float2 v0 = make_float2(acc[mi][ni][0], acc[mi][ni][1]);
            float2 v1 = make_float2(acc[mi][ni][2], acc[mi][ni][3]);
            if (epi == 1) {
                v0.x = fmaxf(v0.x, 0.f); v0.y = fmaxf(v0.y, 0.f);
                v1.x = fmaxf(v1.x, 0.f); v1.y = fmaxf(v1.y, 0.f);
            } else if (epi == 2) {
                const float2 r0 = *reinterpret_cast<const float2*>(R + i0);
                const float2 r1 = *reinterpret_cast<const float2*>(R + i1);
                v0.x += r0.x; v0.y += r0.y;
                v1.x += r1.x; v1.y += r1.y;
            }
            *reinterpret_cast<float2*>(C + i0) = v0;
            *reinterpret_cast<float2*>(C + i1) = v1;
        }
    }
}

__global__ void __launch_bounds__(256, 2) tgemm_nt(
    const float* __restrict__ A, const float* __restrict__ B,
    float* __restrict__ C, const float* __restrict__ R,
    int K, int lda, int ldb, int ldc, int epi)
{
    extern __shared__ unsigned smg[];
    tgemm_body(A, B, C, R, K, lda, ldb, ldc, epi,
               blockIdx.y * 128, blockIdx.x * 128, smg);
}

// Fused QKV: one launch, grid (12, 64). blockIdx.x>>2 selects W/output.
__global__ void __launch_bounds__(256, 2) qkv_gemm(
    const float* __restrict__ A,
    const float* __restrict__ Wq, const float* __restrict__ Wk,
    const float* __restrict__ Wv,
    float* __restrict__ q, float* __restrict__ k, float* __restrict__ v)
{
    extern __shared__ unsigned smg[];
    const int which = blockIdx.x >> 2;
    const int n0 = (blockIdx.x & 3) * 128;
    const float* B = (which == 0) ? Wq : (which == 1) ? Wk : Wv;
    float* C = (which == 0) ? q : (which == 1) ? k : v;
    tgemm_body(A, B, C, nullptr, DD, DD, DD, DD, 0,
               blockIdx.y * 128, n0, smg);
}

// ----------------------------------------------- tf32 tensor flash attention
// 128 q-rows x 64 k-cols per tile, 8 warps, online softmax on mma fragments.
// smem: Qsm[128][68] | Ks[64][68] | Vs[64][72] | Ps[128][68] (bias staging + P)
#define FA_SMEM_BYTES 105472

__global__ void __launch_bounds__(256, 2) flash_tf32_kernel(
    const float* __restrict__ Q, const float* __restrict__ Kg,
    const float* __restrict__ V, const float* __restrict__ bias,
    float* __restrict__ O)
{
    extern __shared__ float sm[];
    float* Qsm = sm;                          // [128][68]
    float* Ks  = sm + 8704;                   // [64][68]
    float* Vs  = sm + 8704 + 4352;            // [64][72]
    float* Ps  = sm + 8704 + 4352 + 4608;     // [128][68]

    const int tid = threadIdx.x, lane = tid & 31, w = tid >> 5;
    const int fr = lane >> 2, fc = lane & 3;
    const int q0 = blockIdx.x * 128;
    const int bh = blockIdx.y;
    const int b = bh >> 3, h = bh & 7;

    const float* Qb = Q  + (size_t)b * SS * DD + h * HDQ;
    const float* Kb = Kg + (size_t)b * SS * DD + h * HDQ;
    const float* Vb = V  + (size_t)b * SS * DD + h * HDQ;
    const float* Bb = bias + (size_t)bh * SS * SS;

    const int rlo = 16 * w + fr;
    const int rhi = rlo + 8;

    // ---- stage Q [128][64] -> Qsm, coalesced ----
    #pragma unroll
    for (int t = 0; t < 8; ++t) {
        const int idx = tid + t * 256;        // 0..2047 float4 slots
        const int row = idx >> 4, c4 = idx & 15;
        const float4 qv = *reinterpret_cast<const float4*>(
            Qb + (size_t)(q0 + row) * DD + c4 * 4);
        *reinterpret_cast<float4*>(&Qsm[row * 68 + c4 * 4]) = qv;
    }
    __syncthreads();

    float Ox[8][4];
    #pragma unroll
    for (int d = 0; d < 8; ++d)
        #pragma unroll
        for (int j = 0; j < 4; ++j) Ox[d][j] = 0.f;
    float m0 = -3.4e38f, m1 = -3.4e38f, l0 = 0.f, l1 = 0.f;

    for (int k0 = 0; k0 < SS; k0 += 64) {
        // ---- K,V global -> regs (coalesced) ----
        float4 kr[4], vr[4];
        #pragma unroll
        for (int t = 0; t < 4; ++t) {
            const int idx = tid + t * 256;    // 0..1023
            const int row = idx >> 4, c4 = idx & 15;
            kr[t] = *reinterpret_cast<const float4*>(
                Kb + (size_t)(k0 + row) * DD + c4 * 4);
            vr[t] = *reinterpret_cast<const float4*>(
                Vb + (size_t)(k0 + row) * DD + c4 * 4);
        }
        __syncthreads();   // previous tile PV (Ps, Vs reads) complete
        #pragma unroll
        for (int t = 0; t < 4; ++t) {
            const int idx = tid + t * 256;
            const int row = idx >> 4, c4 = idx & 15;
            *reinterpret_cast<float4*>(&Ks[row * 68 + c4 * 4]) = kr[t];
            *reinterpret_cast<float4*>(&Vs[row * 72 + c4 * 4]) = vr[t];
        }
        // ---- stage bias tile [128][64] -> Ps (coalesced) ----
        #pragma unroll
        for (int t = 0; t < 8; ++t) {
            const int idx = tid + t * 256;
            const int row = idx >> 4, c4 = idx & 15;
            const float4 bv = *reinterpret_cast<const float4*>(
                Bb + (size_t)(q0 + row) * SS + k0 + c4 * 4);
            *reinterpret_cast<float4*>(&Ps[row * 68 + c4 * 4]) = bv;
        }
        __syncthreads();

        // ---- S = bias; S += Q K^T ----
        float Sx[8][4];
        #pragma unroll
        for (int nb = 0; nb < 8; ++nb) {
            const float2 blo = *reinterpret_cast<const float2*>(
                &Ps[rlo * 68 + 8 * nb + 2 * fc]);
            const float2 bhi = *reinterpret_cast<const float2*>(
                &Ps[rhi * 68 + 8 * nb + 2 * fc]);
            Sx[nb][0] = blo.x; Sx[nb][1] = blo.y;
            Sx[nb][2] = bhi.x; Sx[nb][3] = bhi.y;
        }
        #pragma unroll
        for (int kb = 0; kb < 8; ++kb) {
            const unsigned a0 = __float_as_uint(Qsm[rlo * 68 + 8 * kb + fc]);
            const unsigned a1 = __float_as_uint(Qsm[rhi * 68 + 8 * kb + fc]);
            const unsigned a2 = __float_as_uint(Qsm[rlo * 68 + 8 * kb + fc + 4]);
            const unsigned a3 = __float_as_uint(Qsm[rhi * 68 + 8 * kb + fc + 4]);
            #pragma unroll
            for (int nb = 0; nb < 8; ++nb) {
                const unsigned b0 = __float_as_uint(Ks[(8 * nb + fr) * 68 + 8 * kb + fc]);
                const unsigned b1 = __float_as_uint(Ks[(8 * nb + fr) * 68 + 8 * kb + fc + 4]);
                mma_tf32(Sx[nb], a0, a1, a2, a3, b0, b1);
            }
        }

        // ---- online softmax (rows rlo via c0,c1 ; rows rhi via c2,c3) ----
        float mxlo = -3.4e38f, mxhi = -3.4e38f;
        #pragma unroll
        for (int nb = 0; nb < 8; ++nb) {
            mxlo = fmaxf(mxlo, fmaxf(Sx[nb][0], Sx[nb][1]));
            mxhi = fmaxf(mxhi, fmaxf(Sx[nb][2], Sx[nb][3]));
        }
        mxlo = fmaxf(mxlo, __shfl_xor_sync(0xffffffffu, mxlo, 1));
        mxlo = fmaxf(mxlo, __shfl_xor_sync(0xffffffffu, mxlo, 2));
        mxhi = fmaxf(mxhi, __shfl_xor_sync(0xffffffffu, mxhi, 1));
        mxhi = fmaxf(mxhi, __shfl_xor_sync(0xffffffffu, mxhi, 2));
        const float Mlo = fmaxf(m0, mxlo), Mhi = fmaxf(m1, mxhi);
        const float sclo = __expf(m0 - Mlo), schi = __expf(m1 - Mhi);
        m0 = Mlo; m1 = Mhi;
        float slo = 0.f, shi = 0.f;
        #pragma unroll
        for (int nb = 0; nb < 8; ++nb) {
            Sx[nb][0] = __expf(Sx[nb][0] - Mlo);
            Sx[nb][1] = __expf(Sx[nb][1] - Mlo);
            Sx[nb][2] = __expf(Sx[nb][2] - Mhi);
            Sx[nb][3] = __expf(Sx[nb][3] - Mhi);
            slo += Sx[nb][0] + Sx[nb][1];
            shi += Sx[nb][2] + Sx[nb][3];
        }
        slo += __shfl_xor_sync(0xffffffffu, slo, 1);
        slo += __shfl_xor_sync(0xffffffffu, slo, 2);
        shi += __shfl_xor_sync(0xffffffffu, shi, 1);
        shi += __shfl_xor_sync(0xffffffffu, shi, 2);
        l0 = l0 * sclo + slo;
        l1 = l1 * schi + shi;
        #pragma unroll
        for (int d = 0; d < 8; ++d) {
            Ox[d][0] *= sclo; Ox[d][1] *= sclo;
            Ox[d][2] *= schi; Ox[d][3] *= schi;
        }
        // ---- write P (own-warp rows only) ----
        #pragma unroll
        for (int nb = 0; nb < 8; ++nb) {
            *reinterpret_cast<float2*>(&Ps[rlo * 68 + 8 * nb + 2 * fc]) =
                make_float2(Sx[nb][0], Sx[nb][1]);
            *reinterpret_cast<float2*>(&Ps[rhi * 68 + 8 * nb + 2 * fc]) =
                make_float2(Sx[nb][2], Sx[nb][3]);
        }
        __syncwarp();

        // ---- O += P V ----
        #pragma unroll
        for (int kb = 0; kb < 8; ++kb) {
            const unsigned p0 = __float_as_uint(Ps[rlo * 68 + 8 * kb + fc]);
            const unsigned p1 = __float_as_uint(Ps[rhi * 68 + 8 * kb + fc]);
            const unsigned p2 = __float_as_uint(Ps[rlo * 68 + 8 * kb + fc + 4]);
            const unsigned p3 = __float_as_uint(Ps[rhi * 68 + 8 * kb + fc + 4]);
            #pragma unroll
            for (int d = 0; d < 8; ++d) {
                const unsigned v0 = __float_as_uint(Vs[(8 * kb + fc) * 72 + 8 * d + fr]);
                const unsigned v1 = __float_as_uint(Vs[(8 * kb + fc + 4) * 72 + 8 * d + fr]);
                mma_tf32(Ox[d], p0, p1, p2, p3, v0, v1);
            }
        }
    }

    // ---- normalize + write ctx [B,S,D] ----
    const float il0 = 1.0f / l0, il1 = 1.0f / l1;
    float* Ob = O + (size_t)b * SS * DD + h * HDQ;
    #pragma unroll
    for (int d = 0; d < 8; ++d) {
        *reinterpret_cast<float2*>(
            Ob + (size_t)(q0 + rlo) * DD + 8 * d + 2 * fc) =
            make_float2(Ox[d][0] * il0, Ox[d][1] * il0);
        *reinterpret_cast<float2*>(
            Ob + (size_t)(q0 + rhi) * DD + 8 * d + 2 * fc) =
            make_float2(Ox[d][2] * il1, Ox[d][3] * il1);
    }
}

// ------------------------------------------------------------------ host ----
extern "C" void kernel_launch(void* const* d_in, const int* in_sizes, int n_in,
                              void* d_out, int out_size)
{
    const float* Wk   = (const float*)d_in[0];
    const float* Wo   = (const float*)d_in[1];
    const float* Wq   = (const float*)d_in[2];
    const float* Wv   = (const float*)d_in[3];
    const float* gm1  = (const float*)d_in[4];
    const float* wi   = (const float*)d_in[5];
    const float* wo   = (const float*)d_in[6];
    const float* gm2  = (const float*)d_in[7];
    const float* x    = (const float*)d_in[8];
    const float* bias = (const float*)d_in[9];
    float* out = (float*)d_out;

    float *h, *q, *k, *v, *ctx, *y, *h2, *ff;
    cudaGetSymbolAddress((void**)&h,   g_h);
    cudaGetSymbolAddress((void**)&q,   g_q);
    cudaGetSymbolAddress((void**)&k,   g_k);
    cudaGetSymbolAddress((void**)&v,   g_v);
    cudaGetSymbolAddress((void**)&ctx, g_ctx);
    cudaGetSymbolAddress((void**)&y,   g_y);
    cudaGetSymbolAddress((void**)&h2,  g_h2);
    cudaGetSymbolAddress((void**)&ff,  g_ff);

    cudaFuncSetAttribute(flash_tf32_kernel,
                         cudaFuncAttributeMaxDynamicSharedMemorySize,
                         FA_SMEM_BYTES);
    cudaFuncSetAttribute(tgemm_nt,
                         cudaFuncAttributeMaxDynamicSharedMemorySize,
                         GEMM_SMEM_BYTES);
    cudaFuncSetAttribute(qkv_gemm,
                         cudaFuncAttributeMaxDynamicSharedMemorySize,
                         GEMM_SMEM_BYTES);

    // 1. h = rmsnorm(x) * g1
    rmsnorm_kernel<<<ROWS, 128>>>(x, gm1, h);

    // 2. fused q/k/v = h @ W^T   (single launch, grid 12x64)
    qkv_gemm<<<dim3(12, ROWS / 128), 256, GEMM_SMEM_BYTES>>>(
        h, Wq, Wk, Wv, q, k, v);

    // 3. fused attention: ctx = softmax(q k^T + bias) v, written as [B,S,D]
    flash_tf32_kernel<<<dim3(SS / 128, BH), 256, FA_SMEM_BYTES>>>(
        q, k, v, bias, ctx);

    // 4. y = x + ctx @ Wo^T
    tgemm_nt<<<dim3(DD / 128, ROWS / 128), 256, GEMM_SMEM_BYTES>>>(
        ctx, Wo, y, x, DD, DD, DD, DD, 2);

    // 5. h2 = rmsnorm(y) * g2
    rmsnorm_kernel<<<ROWS, 128>>>(y, gm2, h2);

    // 6. ff = relu(h2 @ wi^T)   (M=8192, N=2048, K=512)
    tgemm_nt<<<dim3(DFF / 128, ROWS / 128), 256, GEMM_SMEM_BYTES>>>(
        h2, wi, ff, nullptr, DD, DD, DD, DFF, 1);

    // 7. out = y + ff @ wo^T    (M=8192, N=512, K=2048)
    tgemm_nt<<<dim3(DD / 128, ROWS / 128), 256, GEMM_SMEM_BYTES>>>(
        ff, wo, out, y, DFF, DFF, DFF, DD, 2);
}